// round 7
// baseline (speedup 1.0000x reference)
#include <cuda_runtime.h>
#include <cuda_bf16.h>
#include <cstdint>
#include <math.h>

// Problem constants (static per reference)
#define NBATCH 8
#define LQ     5440
#define TTOK   (NBATCH*LQ)      // 43520
#define DIM    256
#define NHEAD  8
#define HD     32
#define NLVL   4
#define NPT    4
#define DFF    1024

// Scratch (device globals; no runtime allocation)
__device__ __nv_bfloat16 g_srcb [(size_t)TTOK*DIM];
__device__ __nv_bfloat16 g_qb   [(size_t)TTOK*DIM];
__device__ __nv_bfloat16 g_valbf[(size_t)TTOK*DIM];
__device__ float         g_offattn[(size_t)TTOK*384];
__device__ __nv_bfloat16 g_sampb[(size_t)TTOK*DIM];
__device__ float         g_x    [(size_t)TTOK*DIM];
__device__ __nv_bfloat16 g_xb   [(size_t)TTOK*DIM];
__device__ __nv_bfloat16 g_hidb [(size_t)TTOK*DFF];
// Transposed ([N][K]) bf16 weights
__device__ __nv_bfloat16 g_wtv  [256*256];
__device__ __nv_bfloat16 g_wtoa [384*256];
__device__ __nv_bfloat16 g_wtout[256*256];
__device__ __nv_bfloat16 g_wt1  [1024*256];
__device__ __nv_bfloat16 g_wt2  [256*1024];
__device__ float         g_boa  [384];

// ---------------------------------------------------------------------------
// Helpers
// ---------------------------------------------------------------------------
__device__ __forceinline__ uint32_t smem_u32(const void* p) {
    uint32_t a;
    asm("{ .reg .u64 t; cvta.to.shared.u64 t, %1; cvt.u32.u64 %0, t; }" : "=r"(a) : "l"(p));
    return a;
}
__device__ __forceinline__ void cpasync16(uint32_t dst, const void* src) {
    asm volatile("cp.async.cg.shared.global [%0], [%1], 16;" :: "r"(dst), "l"(src));
}
#define CP_COMMIT() asm volatile("cp.async.commit_group;" ::: "memory")
#define CP_WAIT1()  asm volatile("cp.async.wait_group 1;" ::: "memory")

__device__ __forceinline__ void ldmx4(uint32_t& f0, uint32_t& f1, uint32_t& f2, uint32_t& f3,
                                      uint32_t addr) {
    asm volatile("ldmatrix.sync.aligned.m8n8.x4.shared.b16 {%0,%1,%2,%3}, [%4];"
                 : "=r"(f0), "=r"(f1), "=r"(f2), "=r"(f3) : "r"(addr));
}
__device__ __forceinline__ void mma_bf16(float* c, uint32_t a0, uint32_t a1,
                                         uint32_t a2, uint32_t a3,
                                         uint32_t b0, uint32_t b1) {
    asm volatile(
        "mma.sync.aligned.m16n8k16.row.col.f32.bf16.bf16.f32 "
        "{%0,%1,%2,%3}, {%4,%5,%6,%7}, {%8,%9}, {%0,%1,%2,%3};"
        : "+f"(c[0]), "+f"(c[1]), "+f"(c[2]), "+f"(c[3])
        : "r"(a0), "r"(a1), "r"(a2), "r"(a3), "r"(b0), "r"(b1));
}

// ---------------------------------------------------------------------------
// One-shot prep: weight transposes (fp32 [K][N] -> bf16 [N][K]), bias concat,
// src/q bf16 conversion. Single launch.
// ---------------------------------------------------------------------------
#define PREP_WBLK 2944
#define PREP_ABLK 10880
__global__ void prep_kernel(const float* __restrict__ Wv, const float* __restrict__ Wo,
                            const float* __restrict__ Wa, const float* __restrict__ Wout,
                            const float* __restrict__ W1, const float* __restrict__ W2,
                            const float* __restrict__ bo, const float* __restrict__ ba,
                            const float4* __restrict__ src, const float4* __restrict__ pos,
                            __nv_bfloat16* __restrict__ wtv, __nv_bfloat16* __restrict__ wtoa,
                            __nv_bfloat16* __restrict__ wtout, __nv_bfloat16* __restrict__ wt1,
                            __nv_bfloat16* __restrict__ wt2, float* __restrict__ boa,
                            __nv_bfloat16* __restrict__ srcb, __nv_bfloat16* __restrict__ qb)
{
    int b = blockIdx.x;
    if (b < PREP_WBLK) {
        int idx = b * 256 + threadIdx.x;  // 0..753663
        float v; __nv_bfloat16* dst;
        if (idx < 65536) {                       // Wv [256,256]
            int n = idx >> 8, k = idx & 255; v = Wv[k * 256 + n]; dst = wtv + idx;
        } else if (idx < 163840) {               // Woa [384,256] = [Wo|Wa]
            int j = idx - 65536; int n = j >> 8, k = j & 255;
            v = (n < 256) ? Wo[k * 256 + n] : Wa[k * 128 + (n - 256)]; dst = wtoa + j;
        } else if (idx < 229376) {               // Wout [256,256]
            int j = idx - 163840; int n = j >> 8, k = j & 255; v = Wout[k * 256 + n]; dst = wtout + j;
        } else if (idx < 491520) {               // W1 [1024,256]
            int j = idx - 229376; int n = j >> 8, k = j & 255; v = W1[k * 1024 + n]; dst = wt1 + j;
        } else {                                 // W2 [256,1024]
            int j = idx - 491520; int n = j >> 10, k = j & 1023; v = W2[k * 256 + n]; dst = wt2 + j;
        }
        *dst = __float2bfloat16(v);
    } else if (b < PREP_WBLK + PREP_ABLK) {
        int idx = (b - PREP_WBLK) * 256 + threadIdx.x;   // float4 index
        float4 s = src[idx], p = pos[idx];
        __nv_bfloat162 s01 = __float22bfloat162_rn(make_float2(s.x, s.y));
        __nv_bfloat162 s23 = __float22bfloat162_rn(make_float2(s.z, s.w));
        __nv_bfloat162 q01 = __float22bfloat162_rn(make_float2(s.x + p.x, s.y + p.y));
        __nv_bfloat162 q23 = __float22bfloat162_rn(make_float2(s.z + p.z, s.w + p.w));
        ((uint2*)srcb)[idx] = make_uint2(*(uint32_t*)&s01, *(uint32_t*)&s23);
        ((uint2*)qb)[idx]   = make_uint2(*(uint32_t*)&q01, *(uint32_t*)&q23);
    } else {
        int i = threadIdx.x;
        if (i < 384) boa[i] = (i < 256) ? bo[i] : ba[i - 256];
    }
}

// ---------------------------------------------------------------------------
// bf16 tensor GEMM (128x128 tile), cp.async 3-stage + ldmatrix. As in R6.
// ---------------------------------------------------------------------------
#define BK 64
template<int ACT, int OBF>
__global__ void __launch_bounds__(256, 2)
mma_gemm(const __nv_bfloat16* __restrict__ A, const __nv_bfloat16* __restrict__ Wt,
         const float* __restrict__ bias, float* __restrict__ C,
         __nv_bfloat16* __restrict__ C16, int K, int Nc, int mtiles)
{
    extern __shared__ char smem[];
    const uint32_t sbase = smem_u32(smem);

    const int tid = threadIdx.x;
    const int wid = tid >> 5, lane = tid & 31;
    const int g = lane >> 2, tg = lane & 3;
    const int wm = wid & 1, wn = wid >> 1;
    const int mt = blockIdx.x % mtiles;
    const int nt = blockIdx.x / mtiles;
    const int row0 = mt * 128, col0 = nt * 128;

    const int a_r  = (lane & 7) + ((lane >> 3) & 1) * 8;
    const int a_kh = (lane >> 4) & 1;
    const int b_r  = (lane & 7) + ((lane >> 4) << 3);
    const int b_kh = (lane >> 3) & 1;

    float acc[4][4][4];
#pragma unroll
    for (int i = 0; i < 4; i++)
#pragma unroll
        for (int j = 0; j < 4; j++)
#pragma unroll
            for (int k = 0; k < 4; k++) acc[i][j][k] = 0.f;

    auto load_chunk = [&](int k0, int st) {
#pragma unroll
        for (int i = 0; i < 4; i++) {
            int idx = tid + i * 256;
            int r = idx >> 3, gc = idx & 7;
            uint32_t so = (uint32_t)(r * 128 + ((gc ^ (r & 7)) << 4));
            cpasync16(sbase + st * 16384 + so, A + (size_t)(row0 + r) * K + k0 + gc * 8);
            cpasync16(sbase + 49152 + st * 16384 + so, Wt + (size_t)(col0 + r) * K + k0 + gc * 8);
        }
    };

    const int nchunk = K / BK;
    load_chunk(0, 0);
    CP_COMMIT();
    if (nchunk > 1) load_chunk(BK, 1);
    CP_COMMIT();

    for (int ch = 0; ch < nchunk; ch++) {
        CP_WAIT1();
        __syncthreads();
        if (ch + 2 < nchunk) load_chunk((ch + 2) * BK, (ch + 2) % 3);
        CP_COMMIT();

        const uint32_t Ab = sbase + (ch % 3) * 16384;
        const uint32_t Bb = sbase + 49152 + (ch % 3) * 16384;
#pragma unroll
        for (int ks = 0; ks < 4; ks++) {
            uint32_t bf[4][2];
#pragma unroll
            for (int np = 0; np < 2; np++) {
                int r = wn * 32 + np * 16 + b_r;
                uint32_t addr = Bb + r * 128 + (((ks * 2 + b_kh) ^ (r & 7)) << 4);
                ldmx4(bf[np * 2][0], bf[np * 2][1], bf[np * 2 + 1][0], bf[np * 2 + 1][1], addr);
            }
#pragma unroll
            for (int mf = 0; mf < 4; mf++) {
                int r = wm * 64 + mf * 16 + a_r;
                uint32_t addr = Ab + r * 128 + (((ks * 2 + a_kh) ^ (r & 7)) << 4);
                uint32_t a0, a1, a2, a3;
                ldmx4(a0, a1, a2, a3, addr);
#pragma unroll
                for (int nf = 0; nf < 4; nf++)
                    mma_bf16(acc[mf][nf], a0, a1, a2, a3, bf[nf][0], bf[nf][1]);
            }
        }
    }

#pragma unroll
    for (int mf = 0; mf < 4; mf++) {
#pragma unroll
        for (int nf = 0; nf < 4; nf++) {
            int row = row0 + wm * 64 + mf * 16 + g;
            int col = col0 + wn * 32 + nf * 8 + tg * 2;
            float b0 = bias[col], b1 = bias[col + 1];
            float o[4];
            o[0] = acc[mf][nf][0] + b0; o[1] = acc[mf][nf][1] + b1;
            o[2] = acc[mf][nf][2] + b0; o[3] = acc[mf][nf][3] + b1;
            if (ACT) {
#pragma unroll
                for (int i = 0; i < 4; i++) o[i] = fmaxf(o[i], 0.f);
            }
            if (OBF) {
                *(__nv_bfloat162*)(&C16[(size_t)row * Nc + col]) =
                    __float22bfloat162_rn(make_float2(o[0], o[1]));
                *(__nv_bfloat162*)(&C16[(size_t)(row + 8) * Nc + col]) =
                    __float22bfloat162_rn(make_float2(o[2], o[3]));
            } else {
                *(float2*)(&C[(size_t)row * Nc + col]) = make_float2(o[0], o[1]);
                *(float2*)(&C[(size_t)(row + 8) * Nc + col]) = make_float2(o[2], o[3]);
            }
        }
    }
}

// ---------------------------------------------------------------------------
// bf16 GEMM with fused residual + LayerNorm epilogue.
// CTA tile 128 x 256 (row-complete). 8 warps = 2m x 4n, warp tile 64x64.
// O = LN( A@Wt^T + bias + R ) * gam + bet ; optional bf16 copy O16.
// Smem: 3 stages x (A 16KB + B 32KB) = 144KB; 1 CTA/SM.
// ---------------------------------------------------------------------------
template<int OB16>
__global__ void __launch_bounds__(256, 1)
gemm_ln(const __nv_bfloat16* __restrict__ A, const __nv_bfloat16* __restrict__ Wt,
        const float* __restrict__ bias, const float* __restrict__ R,
        const float* __restrict__ gam, const float* __restrict__ bet,
        float* __restrict__ O, __nv_bfloat16* __restrict__ O16, int K)
{
    extern __shared__ char smem[];
    const uint32_t sbase = smem_u32(smem);

    const int tid = threadIdx.x;
    const int wid = tid >> 5, lane = tid & 31;
    const int g = lane >> 2, tg = lane & 3;
    const int wm = wid & 1, wn = wid >> 1;
    const int row0 = blockIdx.x * 128;

    const int a_r  = (lane & 7) + ((lane >> 3) & 1) * 8;
    const int a_kh = (lane >> 4) & 1;
    const int b_r  = (lane & 7) + ((lane >> 4) << 3);
    const int b_kh = (lane >> 3) & 1;

    float acc[4][8][4];
#pragma unroll
    for (int i = 0; i < 4; i++)
#pragma unroll
        for (int j = 0; j < 8; j++)
#pragma unroll
            for (int k = 0; k < 4; k++) acc[i][j][k] = 0.f;

    auto load_chunk = [&](int k0, int st) {
        uint32_t base = sbase + st * 49152;
#pragma unroll
        for (int i = 0; i < 4; i++) {       // A: 128 rows x 8 granules
            int idx = tid + i * 256;
            int r = idx >> 3, gc = idx & 7;
            cpasync16(base + r * 128 + ((gc ^ (r & 7)) << 4),
                      A + (size_t)(row0 + r) * K + k0 + gc * 8);
        }
#pragma unroll
        for (int i = 0; i < 8; i++) {       // B: 256 rows x 8 granules
            int idx = tid + i * 256;
            int r = idx >> 3, gc = idx & 7;
            cpasync16(base + 16384 + r * 128 + ((gc ^ (r & 7)) << 4),
                      Wt + (size_t)r * K + k0 + gc * 8);
        }
    };

    const int nchunk = K / BK;
    load_chunk(0, 0);
    CP_COMMIT();
    if (nchunk > 1) load_chunk(BK, 1);
    CP_COMMIT();

    for (int ch = 0; ch < nchunk; ch++) {
        CP_WAIT1();
        __syncthreads();
        if (ch + 2 < nchunk) load_chunk((ch + 2) * BK, (ch + 2) % 3);
        CP_COMMIT();

        const uint32_t Ab = sbase + (ch % 3) * 49152;
        const uint32_t Bb = Ab + 16384;
#pragma unroll
        for (int ks = 0; ks < 4; ks++) {
            uint32_t bf[8][2];
#pragma unroll
            for (int np = 0; np < 4; np++) {
                int r = wn * 64 + np * 16 + b_r;
                uint32_t addr = Bb + r * 128 + (((ks * 2 + b_kh) ^ (r & 7)) << 4);
                ldmx4(bf[np * 2][0], bf[np * 2][1], bf[np * 2 + 1][0], bf[np * 2 + 1][1], addr);
            }
#pragma unroll
            for (int mf = 0; mf < 4; mf++) {
                int r = wm * 64 + mf * 16 + a_r;
                uint32_t addr = Ab + r * 128 + (((ks * 2 + a_kh) ^ (r & 7)) << 4);
                uint32_t a0, a1, a2, a3;
                ldmx4(a0, a1, a2, a3, addr);
#pragma unroll
                for (int nf = 0; nf < 8; nf++)
                    mma_bf16(acc[mf][nf], a0, a1, a2, a3, bf[nf][0], bf[nf][1]);
            }
        }
    }

    // ---- Epilogue: bias + residual, then LayerNorm over the 256 cols ----
#pragma unroll
    for (int mf = 0; mf < 4; mf++) {
        int row = row0 + wm * 64 + mf * 16 + g;
#pragma unroll
        for (int nf = 0; nf < 8; nf++) {
            int col = wn * 64 + nf * 8 + tg * 2;
            float b0 = bias[col], b1 = bias[col + 1];
            float2 r0 = *(const float2*)&R[(size_t)row * 256 + col];
            float2 r1 = *(const float2*)&R[(size_t)(row + 8) * 256 + col];
            acc[mf][nf][0] += b0 + r0.x; acc[mf][nf][1] += b1 + r0.y;
            acc[mf][nf][2] += b0 + r1.x; acc[mf][nf][3] += b1 + r1.y;
        }
    }

    // per-(row) partial sums over this thread's 16 cols, then tg-group shfl
    float psum[4][2], psq[4][2];
#pragma unroll
    for (int mf = 0; mf < 4; mf++)
#pragma unroll
        for (int h = 0; h < 2; h++) {
            float s = 0.f, q = 0.f;
#pragma unroll
            for (int nf = 0; nf < 8; nf++) {
                float v0 = acc[mf][nf][2 * h + 0], v1 = acc[mf][nf][2 * h + 1];
                s += v0 + v1; q += v0 * v0 + v1 * v1;
            }
            s += __shfl_xor_sync(0xffffffffu, s, 1);
            s += __shfl_xor_sync(0xffffffffu, s, 2);
            q += __shfl_xor_sync(0xffffffffu, q, 1);
            q += __shfl_xor_sync(0xffffffffu, q, 2);
            psum[mf][h] = s; psq[mf][h] = q;
        }

    __syncthreads();            // smem stages no longer needed
    float* rs = (float*)smem;   // [128][4]
    float* rq = rs + 512;       // [128][4]
    if (tg == 0) {
#pragma unroll
        for (int mf = 0; mf < 4; mf++)
#pragma unroll
            for (int h = 0; h < 2; h++) {
                int r = wm * 64 + mf * 16 + g + 8 * h;
                rs[r * 4 + wn] = psum[mf][h];
                rq[r * 4 + wn] = psq[mf][h];
            }
    }
    __syncthreads();

    float mean_[4][2], rstd_[4][2];
#pragma unroll
    for (int mf = 0; mf < 4; mf++)
#pragma unroll
        for (int h = 0; h < 2; h++) {
            int r = wm * 64 + mf * 16 + g + 8 * h;
            float s = rs[r * 4 + 0] + rs[r * 4 + 1] + rs[r * 4 + 2] + rs[r * 4 + 3];
            float q = rq[r * 4 + 0] + rq[r * 4 + 1] + rq[r * 4 + 2] + rq[r * 4 + 3];
            float mean = s * (1.f / 256.f);
            float var = q * (1.f / 256.f) - mean * mean;
            mean_[mf][h] = mean;
            rstd_[mf][h] = rsqrtf(var + 1e-5f);
        }

#pragma unroll
    for (int mf = 0; mf < 4; mf++) {
        int row = row0 + wm * 64 + mf * 16 + g;
#pragma unroll
        for (int nf = 0; nf < 8; nf++) {
            int col = wn * 64 + nf * 8 + tg * 2;
            float g0 = gam[col], g1 = gam[col + 1];
            float e0 = bet[col], e1 = bet[col + 1];
            float y0 = (acc[mf][nf][0] - mean_[mf][0]) * rstd_[mf][0] * g0 + e0;
            float y1 = (acc[mf][nf][1] - mean_[mf][0]) * rstd_[mf][0] * g1 + e1;
            float y2 = (acc[mf][nf][2] - mean_[mf][1]) * rstd_[mf][1] * g0 + e0;
            float y3 = (acc[mf][nf][3] - mean_[mf][1]) * rstd_[mf][1] * g1 + e1;
            *(float2*)(&O[(size_t)row * 256 + col]) = make_float2(y0, y1);
            *(float2*)(&O[(size_t)(row + 8) * 256 + col]) = make_float2(y2, y3);
            if (OB16) {
                *(__nv_bfloat162*)(&O16[(size_t)row * 256 + col]) =
                    __float22bfloat162_rn(make_float2(y0, y1));
                *(__nv_bfloat162*)(&O16[(size_t)(row + 8) * 256 + col]) =
                    __float22bfloat162_rn(make_float2(y2, y3));
            }
        }
    }
}

// ---------------------------------------------------------------------------
// Deformable sampling with fused softmax. Warp per token (unchanged from R6).
// ---------------------------------------------------------------------------
__global__ void __launch_bounds__(256)
sample_kernel(const __nv_bfloat16* __restrict__ valbf,
              const float* __restrict__ offattn,
              const float* __restrict__ ref,
              __nv_bfloat16* __restrict__ sampb)
{
    const int t = blockIdx.x * 8 + (threadIdx.x >> 5);
    const int lane = threadIdx.x & 31;
    const int h = lane >> 2;
    const int d8 = lane & 3;
    const int n = t / LQ;

    const float* rowp = offattn + (size_t)t * 384;
    const float* lp = rowp + 256 + h * 16;
    const float* op = rowp + h * 32;

    float lg[16];
    float mx = -1e30f;
#pragma unroll
    for (int j = 0; j < 16; j++) { lg[j] = lp[j]; mx = fmaxf(mx, lg[j]); }
    float ssum = 0.f;
#pragma unroll
    for (int j = 0; j < 16; j++) { lg[j] = expf(lg[j] - mx); ssum += lg[j]; }
    const float inv = 1.f / ssum;

    const int Hs[4] = {64, 32, 16, 8};
    const int St[4] = {0, 4096, 5120, 5376};

    float acc[8];
#pragma unroll
    for (int i = 0; i < 8; i++) acc[i] = 0.f;

#pragma unroll
    for (int l = 0; l < NLVL; l++) {
        const int H = Hs[l];
        const int W = Hs[l];
        const float fH = (float)H, fW = (float)W;
        const float invW = 1.f / fW, invH = 1.f / fH;
        const float refx = ref[((size_t)t * NLVL + l) * 2 + 0];
        const float refy = ref[((size_t)t * NLVL + l) * 2 + 1];
        const uint4* vb = (const uint4*)(valbf + ((size_t)(n * LQ + St[l])) * DIM + h * HD + d8 * 8);
#pragma unroll
        for (int p = 0; p < NPT; p++) {
            float ox = op[(l * NPT + p) * 2 + 0];
            float oy = op[(l * NPT + p) * 2 + 1];
            float xf = (refx + ox * invW) * fW - 0.5f;
            float yf = (refy + oy * invH) * fH - 0.5f;
            float x0f = floorf(xf), y0f = floorf(yf);
            int x0 = (int)x0f, y0 = (int)y0f;
            float wx1 = xf - x0f, wy1 = yf - y0f;
            float wx0 = 1.f - wx1, wy0 = 1.f - wy1;
            float w = lg[l * NPT + p] * inv;

            bool xin0 = (x0 >= 0) & (x0 < W);
            bool xin1 = (x0 + 1 >= 0) & (x0 + 1 < W);
            bool yin0 = (y0 >= 0) & (y0 < H);
            bool yin1 = (y0 + 1 >= 0) & (y0 + 1 < H);

            float cw[4] = { w * wy0 * wx0, w * wy0 * wx1, w * wy1 * wx0, w * wy1 * wx1 };
            bool vld[4] = { yin0 && xin0, yin0 && xin1, yin1 && xin0, yin1 && xin1 };
            int  idx[4] = { y0 * W + x0, y0 * W + x0 + 1, (y0 + 1) * W + x0, (y0 + 1) * W + x0 + 1 };
#pragma unroll
            for (int cnr = 0; cnr < 4; cnr++) {
                uint4 u = make_uint4(0u, 0u, 0u, 0u);
                if (vld[cnr]) u = vb[(size_t)idx[cnr] * (DIM / 8)];
                const __nv_bfloat162* q2 = (const __nv_bfloat162*)&u;
                float c = cw[cnr];
#pragma unroll
                for (int j = 0; j < 4; j++) {
                    float2 f = __bfloat1622float2(q2[j]);
                    acc[2 * j + 0] = fmaf(f.x, c, acc[2 * j + 0]);
                    acc[2 * j + 1] = fmaf(f.y, c, acc[2 * j + 1]);
                }
            }
        }
    }
    __nv_bfloat162 ob[4];
#pragma unroll
    for (int j = 0; j < 4; j++)
        ob[j] = __float22bfloat162_rn(make_float2(acc[2 * j], acc[2 * j + 1]));
    *(uint4*)(sampb + (size_t)t * DIM + h * HD + d8 * 8) = *(uint4*)ob;
}

// ---------------------------------------------------------------------------
extern "C" void kernel_launch(void* const* d_in, const int* in_sizes, int n_in,
                              void* d_out, int out_size)
{
    const float* src  = (const float*)d_in[0];
    const float* pos  = (const float*)d_in[1];
    const float* refp = (const float*)d_in[2];
    const float* Wv   = (const float*)d_in[4];
    const float* bv   = (const float*)d_in[5];
    const float* Wo   = (const float*)d_in[6];
    const float* bo   = (const float*)d_in[7];
    const float* Wa   = (const float*)d_in[8];
    const float* ba   = (const float*)d_in[9];
    const float* Wout = (const float*)d_in[10];
    const float* bout = (const float*)d_in[11];
    const float* g1   = (const float*)d_in[12];
    const float* be1  = (const float*)d_in[13];
    const float* W1   = (const float*)d_in[14];
    const float* b1   = (const float*)d_in[15];
    const float* W2   = (const float*)d_in[16];
    const float* b2   = (const float*)d_in[17];
    const float* g2   = (const float*)d_in[18];
    const float* be2  = (const float*)d_in[19];
    float* out = (float*)d_out;

    __nv_bfloat16 *psrcb, *pqb, *pvb, *psampb, *pxb, *phidb;
    __nv_bfloat16 *wtv, *wtoa, *wtout, *wt1, *wt2;
    float *poa, *px, *pboa;
    cudaGetSymbolAddress((void**)&psrcb, g_srcb);
    cudaGetSymbolAddress((void**)&pqb,   g_qb);
    cudaGetSymbolAddress((void**)&pvb,   g_valbf);
    cudaGetSymbolAddress((void**)&poa,   g_offattn);
    cudaGetSymbolAddress((void**)&psampb,g_sampb);
    cudaGetSymbolAddress((void**)&px,    g_x);
    cudaGetSymbolAddress((void**)&pxb,   g_xb);
    cudaGetSymbolAddress((void**)&phidb, g_hidb);
    cudaGetSymbolAddress((void**)&wtv,   g_wtv);
    cudaGetSymbolAddress((void**)&wtoa,  g_wtoa);
    cudaGetSymbolAddress((void**)&wtout, g_wtout);
    cudaGetSymbolAddress((void**)&wt1,   g_wt1);
    cudaGetSymbolAddress((void**)&wt2,   g_wt2);
    cudaGetSymbolAddress((void**)&pboa,  g_boa);

    const int DSM  = 98304;   // mma_gemm: 3 x (16KB + 16KB)
    const int DSML = 147456;  // gemm_ln:  3 x (16KB + 32KB)
    cudaFuncSetAttribute(mma_gemm<0,0>, cudaFuncAttributeMaxDynamicSharedMemorySize, DSM);
    cudaFuncSetAttribute(mma_gemm<0,1>, cudaFuncAttributeMaxDynamicSharedMemorySize, DSM);
    cudaFuncSetAttribute(mma_gemm<1,1>, cudaFuncAttributeMaxDynamicSharedMemorySize, DSM);
    cudaFuncSetAttribute(gemm_ln<0>,    cudaFuncAttributeMaxDynamicSharedMemorySize, DSML);
    cudaFuncSetAttribute(gemm_ln<1>,    cudaFuncAttributeMaxDynamicSharedMemorySize, DSML);

    // One-shot prep
    prep_kernel<<<PREP_WBLK + PREP_ABLK + 1, 256>>>(
        Wv, Wo, Wa, Wout, W1, W2, bo, ba,
        (const float4*)src, (const float4*)pos,
        wtv, wtoa, wtout, wt1, wt2, pboa, psrcb, pqb);

    const int MT = TTOK / 128;  // 340 M-tiles

    // value (bf16) = src @ Wv + bv
    mma_gemm<0,1><<<MT * 2, 256, DSM>>>(psrcb, wtv, bv, nullptr, pvb, 256, 256, MT);
    // offsets|logits (fp32) = q @ [Woff|Wattn] + [boff|battn]
    mma_gemm<0,0><<<MT * 3, 256, DSM>>>(pqb, wtoa, pboa, poa, nullptr, 256, 384, MT);
    // deformable sampling (softmax fused; bf16 out)
    sample_kernel<<<TTOK / 8, 256>>>(pvb, poa, refp, psampb);
    // x = LN1(src + samp @ Wout + bout)   [fused GEMM + residual + LN]
    gemm_ln<1><<<MT, 256, DSML>>>(psampb, wtout, bout, src, g1, be1, px, pxb, 256);
    // hid (bf16) = relu(x @ W1 + b1)
    mma_gemm<1,1><<<MT * 8, 256, DSM>>>(pxb, wt1, b1, nullptr, phidb, 256, 1024, MT);
    // out = LN2(x + hid @ W2 + b2)        [fused GEMM + residual + LN]
    gemm_ln<0><<<MT, 256, DSML>>>(phidb, wt2, b2, px, g2, be2, out, nullptr, 1024);
}

// round 8
// speedup vs baseline: 1.0583x; 1.0583x over previous
#include <cuda_runtime.h>
#include <cuda_bf16.h>
#include <cstdint>
#include <math.h>

// Problem constants (static per reference)
#define NBATCH 8
#define LQ     5440
#define TTOK   (NBATCH*LQ)      // 43520
#define DIM    256
#define NHEAD  8
#define HD     32
#define NLVL   4
#define NPT    4
#define DFF    1024

// Scratch (device globals; no runtime allocation)
__device__ __nv_bfloat16 g_srcb [(size_t)TTOK*DIM];
__device__ __nv_bfloat16 g_qb   [(size_t)TTOK*DIM];
__device__ __nv_bfloat16 g_valbf[(size_t)TTOK*DIM];
__device__ float         g_offattn[(size_t)TTOK*384];
__device__ __nv_bfloat16 g_sampb[(size_t)TTOK*DIM];
__device__ float         g_src2 [(size_t)TTOK*DIM];
__device__ float         g_x    [(size_t)TTOK*DIM];
__device__ __nv_bfloat16 g_xb   [(size_t)TTOK*DIM];
__device__ __nv_bfloat16 g_hidb [(size_t)TTOK*DFF];
__device__ float         g_ffn  [(size_t)TTOK*DIM];
// Transposed ([N][K]) bf16 weights
__device__ __nv_bfloat16 g_wtv  [256*256];
__device__ __nv_bfloat16 g_wtoa [384*256];
__device__ __nv_bfloat16 g_wtout[256*256];
__device__ __nv_bfloat16 g_wt1  [1024*256];
__device__ __nv_bfloat16 g_wt2  [256*1024];
__device__ float         g_boa  [384];

// ---------------------------------------------------------------------------
// Helpers
// ---------------------------------------------------------------------------
__device__ __forceinline__ uint32_t smem_u32(const void* p) {
    uint32_t a;
    asm("{ .reg .u64 t; cvta.to.shared.u64 t, %1; cvt.u32.u64 %0, t; }" : "=r"(a) : "l"(p));
    return a;
}
__device__ __forceinline__ void cpasync16(uint32_t dst, const void* src) {
    asm volatile("cp.async.cg.shared.global [%0], [%1], 16;" :: "r"(dst), "l"(src));
}
#define CP_COMMIT() asm volatile("cp.async.commit_group;" ::: "memory")
#define CP_WAIT1()  asm volatile("cp.async.wait_group 1;" ::: "memory")

__device__ __forceinline__ void ldmx4(uint32_t& f0, uint32_t& f1, uint32_t& f2, uint32_t& f3,
                                      uint32_t addr) {
    asm volatile("ldmatrix.sync.aligned.m8n8.x4.shared.b16 {%0,%1,%2,%3}, [%4];"
                 : "=r"(f0), "=r"(f1), "=r"(f2), "=r"(f3) : "r"(addr));
}
__device__ __forceinline__ void mma_bf16(float* c, uint32_t a0, uint32_t a1,
                                         uint32_t a2, uint32_t a3,
                                         uint32_t b0, uint32_t b1) {
    asm volatile(
        "mma.sync.aligned.m16n8k16.row.col.f32.bf16.bf16.f32 "
        "{%0,%1,%2,%3}, {%4,%5,%6,%7}, {%8,%9}, {%0,%1,%2,%3};"
        : "+f"(c[0]), "+f"(c[1]), "+f"(c[2]), "+f"(c[3])
        : "r"(a0), "r"(a1), "r"(a2), "r"(a3), "r"(b0), "r"(b1));
}

// ---------------------------------------------------------------------------
// One-shot prep: weight transposes (fp32 [K][N] -> bf16 [N][K]), bias concat,
// src/q bf16 conversion. Single launch.
// ---------------------------------------------------------------------------
#define PREP_WBLK 2944
#define PREP_ABLK 10880
__global__ void prep_kernel(const float* __restrict__ Wv, const float* __restrict__ Wo,
                            const float* __restrict__ Wa, const float* __restrict__ Wout,
                            const float* __restrict__ W1, const float* __restrict__ W2,
                            const float* __restrict__ bo, const float* __restrict__ ba,
                            const float4* __restrict__ src, const float4* __restrict__ pos,
                            __nv_bfloat16* __restrict__ wtv, __nv_bfloat16* __restrict__ wtoa,
                            __nv_bfloat16* __restrict__ wtout, __nv_bfloat16* __restrict__ wt1,
                            __nv_bfloat16* __restrict__ wt2, float* __restrict__ boa,
                            __nv_bfloat16* __restrict__ srcb, __nv_bfloat16* __restrict__ qb)
{
    int b = blockIdx.x;
    if (b < PREP_WBLK) {
        int idx = b * 256 + threadIdx.x;  // 0..753663
        float v; __nv_bfloat16* dst;
        if (idx < 65536) {                       // Wv [256,256]
            int n = idx >> 8, k = idx & 255; v = Wv[k * 256 + n]; dst = wtv + idx;
        } else if (idx < 163840) {               // Woa [384,256] = [Wo|Wa]
            int j = idx - 65536; int n = j >> 8, k = j & 255;
            v = (n < 256) ? Wo[k * 256 + n] : Wa[k * 128 + (n - 256)]; dst = wtoa + j;
        } else if (idx < 229376) {               // Wout [256,256]
            int j = idx - 163840; int n = j >> 8, k = j & 255; v = Wout[k * 256 + n]; dst = wtout + j;
        } else if (idx < 491520) {               // W1 [1024,256]
            int j = idx - 229376; int n = j >> 8, k = j & 255; v = W1[k * 1024 + n]; dst = wt1 + j;
        } else {                                 // W2 [256,1024]
            int j = idx - 491520; int n = j >> 10, k = j & 1023; v = W2[k * 256 + n]; dst = wt2 + j;
        }
        *dst = __float2bfloat16(v);
    } else if (b < PREP_WBLK + PREP_ABLK) {
        int idx = (b - PREP_WBLK) * 256 + threadIdx.x;   // float4 index
        float4 s = src[idx], p = pos[idx];
        __nv_bfloat162 s01 = __float22bfloat162_rn(make_float2(s.x, s.y));
        __nv_bfloat162 s23 = __float22bfloat162_rn(make_float2(s.z, s.w));
        __nv_bfloat162 q01 = __float22bfloat162_rn(make_float2(s.x + p.x, s.y + p.y));
        __nv_bfloat162 q23 = __float22bfloat162_rn(make_float2(s.z + p.z, s.w + p.w));
        ((uint2*)srcb)[idx] = make_uint2(*(uint32_t*)&s01, *(uint32_t*)&s23);
        ((uint2*)qb)[idx]   = make_uint2(*(uint32_t*)&q01, *(uint32_t*)&q23);
    } else {
        int i = threadIdx.x;
        if (i < 384) boa[i] = (i < 256) ? bo[i] : ba[i - 256];
    }
}

// ---------------------------------------------------------------------------
// bf16 tensor GEMM (128x128 tile), cp.async 3-stage + ldmatrix.
// ---------------------------------------------------------------------------
#define BK 64
template<int ACT, int OBF>
__global__ void __launch_bounds__(256, 2)
mma_gemm(const __nv_bfloat16* __restrict__ A, const __nv_bfloat16* __restrict__ Wt,
         const float* __restrict__ bias, float* __restrict__ C,
         __nv_bfloat16* __restrict__ C16, int K, int Nc, int mtiles)
{
    extern __shared__ char smem[];
    const uint32_t sbase = smem_u32(smem);

    const int tid = threadIdx.x;
    const int wid = tid >> 5, lane = tid & 31;
    const int g = lane >> 2, tg = lane & 3;
    const int wm = wid & 1, wn = wid >> 1;
    const int mt = blockIdx.x % mtiles;
    const int nt = blockIdx.x / mtiles;
    const int row0 = mt * 128, col0 = nt * 128;

    const int a_r  = (lane & 7) + ((lane >> 3) & 1) * 8;
    const int a_kh = (lane >> 4) & 1;
    const int b_r  = (lane & 7) + ((lane >> 4) << 3);
    const int b_kh = (lane >> 3) & 1;

    float acc[4][4][4];
#pragma unroll
    for (int i = 0; i < 4; i++)
#pragma unroll
        for (int j = 0; j < 4; j++)
#pragma unroll
            for (int k = 0; k < 4; k++) acc[i][j][k] = 0.f;

    auto load_chunk = [&](int k0, int st) {
#pragma unroll
        for (int i = 0; i < 4; i++) {
            int idx = tid + i * 256;
            int r = idx >> 3, gc = idx & 7;
            uint32_t so = (uint32_t)(r * 128 + ((gc ^ (r & 7)) << 4));
            cpasync16(sbase + st * 16384 + so, A + (size_t)(row0 + r) * K + k0 + gc * 8);
            cpasync16(sbase + 49152 + st * 16384 + so, Wt + (size_t)(col0 + r) * K + k0 + gc * 8);
        }
    };

    const int nchunk = K / BK;
    load_chunk(0, 0);
    CP_COMMIT();
    if (nchunk > 1) load_chunk(BK, 1);
    CP_COMMIT();

    for (int ch = 0; ch < nchunk; ch++) {
        CP_WAIT1();
        __syncthreads();
        if (ch + 2 < nchunk) load_chunk((ch + 2) * BK, (ch + 2) % 3);
        CP_COMMIT();

        const uint32_t Ab = sbase + (ch % 3) * 16384;
        const uint32_t Bb = sbase + 49152 + (ch % 3) * 16384;
#pragma unroll
        for (int ks = 0; ks < 4; ks++) {
            uint32_t bf[4][2];
#pragma unroll
            for (int np = 0; np < 2; np++) {
                int r = wn * 32 + np * 16 + b_r;
                uint32_t addr = Bb + r * 128 + (((ks * 2 + b_kh) ^ (r & 7)) << 4);
                ldmx4(bf[np * 2][0], bf[np * 2][1], bf[np * 2 + 1][0], bf[np * 2 + 1][1], addr);
            }
#pragma unroll
            for (int mf = 0; mf < 4; mf++) {
                int r = wm * 64 + mf * 16 + a_r;
                uint32_t addr = Ab + r * 128 + (((ks * 2 + a_kh) ^ (r & 7)) << 4);
                uint32_t a0, a1, a2, a3;
                ldmx4(a0, a1, a2, a3, addr);
#pragma unroll
                for (int nf = 0; nf < 4; nf++)
                    mma_bf16(acc[mf][nf], a0, a1, a2, a3, bf[nf][0], bf[nf][1]);
            }
        }
    }

#pragma unroll
    for (int mf = 0; mf < 4; mf++) {
#pragma unroll
        for (int nf = 0; nf < 4; nf++) {
            int row = row0 + wm * 64 + mf * 16 + g;
            int col = col0 + wn * 32 + nf * 8 + tg * 2;
            float b0 = bias[col], b1 = bias[col + 1];
            float o[4];
            o[0] = acc[mf][nf][0] + b0; o[1] = acc[mf][nf][1] + b1;
            o[2] = acc[mf][nf][2] + b0; o[3] = acc[mf][nf][3] + b1;
            if (ACT) {
#pragma unroll
                for (int i = 0; i < 4; i++) o[i] = fmaxf(o[i], 0.f);
            }
            if (OBF) {
                *(__nv_bfloat162*)(&C16[(size_t)row * Nc + col]) =
                    __float22bfloat162_rn(make_float2(o[0], o[1]));
                *(__nv_bfloat162*)(&C16[(size_t)(row + 8) * Nc + col]) =
                    __float22bfloat162_rn(make_float2(o[2], o[3]));
            } else {
                *(float2*)(&C[(size_t)row * Nc + col]) = make_float2(o[0], o[1]);
                *(float2*)(&C[(size_t)(row + 8) * Nc + col]) = make_float2(o[2], o[3]);
            }
        }
    }
}

// ---------------------------------------------------------------------------
// Deformable sampling with fused softmax. Warp per token: 8 heads x 4 lanes.
// NEW: offattn row (384 floats) staged via coalesced float4 loads into smem;
// offsets/logits then come from LDS (no more head-strided scalar LDG
// wavefront waste).
// ---------------------------------------------------------------------------
__global__ void __launch_bounds__(256)
sample_kernel(const __nv_bfloat16* __restrict__ valbf,
              const float* __restrict__ offattn,
              const float* __restrict__ ref,
              __nv_bfloat16* __restrict__ sampb)
{
    __shared__ float sh[8][384];
    const int w = threadIdx.x >> 5;
    const int t = blockIdx.x * 8 + w;
    const int lane = threadIdx.x & 31;
    const int h = lane >> 2;
    const int d8 = lane & 3;
    const int n = t / LQ;

    // Cooperative staging of this token's offattn row (1536B, coalesced).
    {
        const float4* rowp4 = (const float4*)(offattn + (size_t)t * 384);
        float4* sh4 = (float4*)sh[w];
#pragma unroll
        for (int i = 0; i < 3; i++) sh4[i * 32 + lane] = rowp4[i * 32 + lane];
    }
    __syncwarp();

    const float* op = sh[w] + h * 32;         // 32 offsets for this head
    const float* lp = sh[w] + 256 + h * 16;   // 16 logits for this head

    float lg[16];
    float mx = -1e30f;
#pragma unroll
    for (int j = 0; j < 16; j++) { lg[j] = lp[j]; mx = fmaxf(mx, lg[j]); }
    float ssum = 0.f;
#pragma unroll
    for (int j = 0; j < 16; j++) { lg[j] = expf(lg[j] - mx); ssum += lg[j]; }
    const float inv = 1.f / ssum;

    const int Hs[4] = {64, 32, 16, 8};
    const int St[4] = {0, 4096, 5120, 5376};

    float acc[8];
#pragma unroll
    for (int i = 0; i < 8; i++) acc[i] = 0.f;

#pragma unroll
    for (int l = 0; l < NLVL; l++) {
        const int H = Hs[l];
        const int W = Hs[l];
        const float fH = (float)H, fW = (float)W;
        const float invW = 1.f / fW, invH = 1.f / fH;
        const float refx = ref[((size_t)t * NLVL + l) * 2 + 0];
        const float refy = ref[((size_t)t * NLVL + l) * 2 + 1];
        const uint4* vb = (const uint4*)(valbf + ((size_t)(n * LQ + St[l])) * DIM + h * HD + d8 * 8);
#pragma unroll
        for (int p = 0; p < NPT; p++) {
            float ox = op[(l * NPT + p) * 2 + 0];
            float oy = op[(l * NPT + p) * 2 + 1];
            float xf = (refx + ox * invW) * fW - 0.5f;
            float yf = (refy + oy * invH) * fH - 0.5f;
            float x0f = floorf(xf), y0f = floorf(yf);
            int x0 = (int)x0f, y0 = (int)y0f;
            float wx1 = xf - x0f, wy1 = yf - y0f;
            float wx0 = 1.f - wx1, wy0 = 1.f - wy1;
            float wgt = lg[l * NPT + p] * inv;

            bool xin0 = (x0 >= 0) & (x0 < W);
            bool xin1 = (x0 + 1 >= 0) & (x0 + 1 < W);
            bool yin0 = (y0 >= 0) & (y0 < H);
            bool yin1 = (y0 + 1 >= 0) & (y0 + 1 < H);

            float cw[4] = { wgt * wy0 * wx0, wgt * wy0 * wx1, wgt * wy1 * wx0, wgt * wy1 * wx1 };
            bool vld[4] = { yin0 && xin0, yin0 && xin1, yin1 && xin0, yin1 && xin1 };
            int  idx[4] = { y0 * W + x0, y0 * W + x0 + 1, (y0 + 1) * W + x0, (y0 + 1) * W + x0 + 1 };
#pragma unroll
            for (int cnr = 0; cnr < 4; cnr++) {
                uint4 u = make_uint4(0u, 0u, 0u, 0u);
                if (vld[cnr]) u = vb[(size_t)idx[cnr] * (DIM / 8)];
                const __nv_bfloat162* q2 = (const __nv_bfloat162*)&u;
                float c = cw[cnr];
#pragma unroll
                for (int j = 0; j < 4; j++) {
                    float2 f = __bfloat1622float2(q2[j]);
                    acc[2 * j + 0] = fmaf(f.x, c, acc[2 * j + 0]);
                    acc[2 * j + 1] = fmaf(f.y, c, acc[2 * j + 1]);
                }
            }
        }
    }
    __nv_bfloat162 ob[4];
#pragma unroll
    for (int j = 0; j < 4; j++)
        ob[j] = __float22bfloat162_rn(make_float2(acc[2 * j], acc[2 * j + 1]));
    *(uint4*)(sampb + (size_t)t * DIM + h * HD + d8 * 8) = *(uint4*)ob;
}

// ---------------------------------------------------------------------------
// LayerNorm over 256: out = LN(a + b) * g + beta. One warp per token.
// Optional bf16 secondary output.
// ---------------------------------------------------------------------------
__global__ void ln_kernel(const float* __restrict__ a, const float* __restrict__ b,
                          const float* __restrict__ g, const float* __restrict__ beta,
                          float* __restrict__ out, __nv_bfloat16* __restrict__ out_b)
{
    const int t = blockIdx.x * 4 + (threadIdx.x >> 5);
    const int lane = threadIdx.x & 31;
    const float* pa = a + (size_t)t * DIM;
    const float* pb = b + (size_t)t * DIM;

    float v[8];
    float s = 0.f;
#pragma unroll
    for (int i = 0; i < 8; i++) {
        int c = lane + i * 32;
        v[i] = pa[c] + pb[c];
        s += v[i];
    }
#pragma unroll
    for (int o = 16; o; o >>= 1) s += __shfl_xor_sync(0xffffffffu, s, o);
    const float mean = s * (1.f / 256.f);
    float var = 0.f;
#pragma unroll
    for (int i = 0; i < 8; i++) { float dd = v[i] - mean; var += dd * dd; }
#pragma unroll
    for (int o = 16; o; o >>= 1) var += __shfl_xor_sync(0xffffffffu, var, o);
    const float rstd = rsqrtf(var * (1.f / 256.f) + 1e-5f);
#pragma unroll
    for (int i = 0; i < 8; i++) {
        int c = lane + i * 32;
        float y = (v[i] - mean) * rstd * g[c] + beta[c];
        out[(size_t)t * DIM + c] = y;
        if (out_b) out_b[(size_t)t * DIM + c] = __float2bfloat16(y);
    }
}

// ---------------------------------------------------------------------------
extern "C" void kernel_launch(void* const* d_in, const int* in_sizes, int n_in,
                              void* d_out, int out_size)
{
    const float* src  = (const float*)d_in[0];
    const float* pos  = (const float*)d_in[1];
    const float* refp = (const float*)d_in[2];
    const float* Wv   = (const float*)d_in[4];
    const float* bv   = (const float*)d_in[5];
    const float* Wo   = (const float*)d_in[6];
    const float* bo   = (const float*)d_in[7];
    const float* Wa   = (const float*)d_in[8];
    const float* ba   = (const float*)d_in[9];
    const float* Wout = (const float*)d_in[10];
    const float* bout = (const float*)d_in[11];
    const float* g1   = (const float*)d_in[12];
    const float* be1  = (const float*)d_in[13];
    const float* W1   = (const float*)d_in[14];
    const float* b1   = (const float*)d_in[15];
    const float* W2   = (const float*)d_in[16];
    const float* b2   = (const float*)d_in[17];
    const float* g2   = (const float*)d_in[18];
    const float* be2  = (const float*)d_in[19];
    float* out = (float*)d_out;

    __nv_bfloat16 *psrcb, *pqb, *pvb, *psampb, *pxb, *phidb;
    __nv_bfloat16 *wtv, *wtoa, *wtout, *wt1, *wt2;
    float *poa, *psrc2, *px, *pffn, *pboa;
    cudaGetSymbolAddress((void**)&psrcb, g_srcb);
    cudaGetSymbolAddress((void**)&pqb,   g_qb);
    cudaGetSymbolAddress((void**)&pvb,   g_valbf);
    cudaGetSymbolAddress((void**)&poa,   g_offattn);
    cudaGetSymbolAddress((void**)&psampb,g_sampb);
    cudaGetSymbolAddress((void**)&psrc2, g_src2);
    cudaGetSymbolAddress((void**)&px,    g_x);
    cudaGetSymbolAddress((void**)&pxb,   g_xb);
    cudaGetSymbolAddress((void**)&phidb, g_hidb);
    cudaGetSymbolAddress((void**)&pffn,  g_ffn);
    cudaGetSymbolAddress((void**)&wtv,   g_wtv);
    cudaGetSymbolAddress((void**)&wtoa,  g_wtoa);
    cudaGetSymbolAddress((void**)&wtout, g_wtout);
    cudaGetSymbolAddress((void**)&wt1,   g_wt1);
    cudaGetSymbolAddress((void**)&wt2,   g_wt2);
    cudaGetSymbolAddress((void**)&pboa,  g_boa);

    const int DSM = 98304;  // 3 stages x (16KB A + 16KB B)
    cudaFuncSetAttribute(mma_gemm<0,0>, cudaFuncAttributeMaxDynamicSharedMemorySize, DSM);
    cudaFuncSetAttribute(mma_gemm<0,1>, cudaFuncAttributeMaxDynamicSharedMemorySize, DSM);
    cudaFuncSetAttribute(mma_gemm<1,1>, cudaFuncAttributeMaxDynamicSharedMemorySize, DSM);

    // One-shot prep
    prep_kernel<<<PREP_WBLK + PREP_ABLK + 1, 256>>>(
        Wv, Wo, Wa, Wout, W1, W2, bo, ba,
        (const float4*)src, (const float4*)pos,
        wtv, wtoa, wtout, wt1, wt2, pboa, psrcb, pqb);

    const int MT = TTOK / 128;  // 340 M-tiles

    // value (bf16) = src @ Wv + bv
    mma_gemm<0,1><<<MT * 2, 256, DSM>>>(psrcb, wtv, bv, nullptr, pvb, 256, 256, MT);
    // offsets|logits (fp32) = q @ [Woff|Wattn] + [boff|battn]
    mma_gemm<0,0><<<MT * 3, 256, DSM>>>(pqb, wtoa, pboa, poa, nullptr, 256, 384, MT);
    // deformable sampling (softmax fused; bf16 out)
    sample_kernel<<<TTOK / 8, 256>>>(pvb, poa, refp, psampb);
    // src2 (fp32) = samp @ Wout + bout
    mma_gemm<0,0><<<MT * 2, 256, DSM>>>(psampb, wtout, bout, psrc2, nullptr, 256, 256, MT);
    // x = LN1(src + src2)  (fp32 + bf16 copies)
    ln_kernel<<<TTOK / 4, 128>>>(src, psrc2, g1, be1, px, pxb);
    // hid (bf16) = relu(x @ W1 + b1)
    mma_gemm<1,1><<<MT * 8, 256, DSM>>>(pxb, wt1, b1, nullptr, phidb, 256, 1024, MT);
    // ffn (fp32) = hid @ W2 + b2
    mma_gemm<0,0><<<MT * 2, 256, DSM>>>(phidb, wt2, b2, pffn, nullptr, 1024, 256, MT);
    // out = LN2(x + ffn)
    ln_kernel<<<TTOK / 4, 128>>>(px, pffn, g2, be2, out, nullptr);
}